// round 13
// baseline (speedup 1.0000x reference)
#include <cuda_runtime.h>

#define PED      512
#define M_ROWS   (PED*PED)          // 262144
#define HDIM     64
#define EDIM     32
#define KTOT     96                 // 32 emb + 64 h
#define NGATES   256
#define MTILE    64
#define WT_STRIDE 260               // padded to kill STS conflicts, keeps 8B align
#define OUT_HALF ((size_t)M_ROWS*HDIM)
#define GEMM_GRID 152

// ---------------- device scratch (no allocations allowed) ----------------
__device__ int g_cnt;
__device__ int g_tile;
__device__ int g_list[M_ROWS];

// ---------------- helpers ----------------
__device__ __forceinline__ unsigned long long pk2(float lo, float hi) {
    unsigned long long r;
    asm("mov.b64 %0, {%1,%2};" : "=l"(r)
        : "r"(__float_as_uint(lo)), "r"(__float_as_uint(hi)));
    return r;
}
__device__ __forceinline__ unsigned long long fma2(unsigned long long a,
                                                   unsigned long long b,
                                                   unsigned long long c) {
    unsigned long long d;
    asm("fma.rn.f32x2 %0, %1, %2, %3;" : "=l"(d) : "l"(a), "l"(b), "l"(c));
    return d;
}
__device__ __forceinline__ float get_lo(unsigned long long v) {
    unsigned lo, hi;
    asm("mov.b64 {%0,%1}, %2;" : "=r"(lo), "=r"(hi) : "l"(v));
    return __uint_as_float(lo);
}
__device__ __forceinline__ float get_hi(unsigned long long v) {
    unsigned lo, hi;
    asm("mov.b64 {%0,%1}, %2;" : "=r"(lo), "=r"(hi) : "l"(v));
    return __uint_as_float(hi);
}
__device__ __forceinline__ float sig_fast(float x) {
    return __fdividef(1.f, 1.f + __expf(-x));
}
__device__ __forceinline__ float tanh_fast(float x) {
    x = fminf(fmaxf(x, -15.f), 15.f);
    float e = __expf(2.f * x);
    return __fdividef(e - 1.f, e + 1.f);
}

// ---------------- kernel 0: reset counters ----------------
__global__ void reset_kernel() { g_cnt = 0; g_tile = 0; }

// ---------------- kernel 1: compact active rows (warp-aggregated) ----------------
__global__ void compact_kernel(const int* __restrict__ nei) {
    int row = blockIdx.x * 256 + threadIdx.x;   // grid covers exactly M_ROWS
    bool act = nei[row] > 0;
    unsigned m = __ballot_sync(0xffffffffu, act);
    int lane = threadIdx.x & 31;
    int base = 0;
    if (lane == 0) base = atomicAdd(&g_cnt, __popc(m));
    base = __shfl_sync(0xffffffffu, base, 0);
    if (act) g_list[base + __popc(m & ((1u << lane) - 1u))] = row;
}

// ---------------- kernel 2: copy inactive rows (h,c pass-through) ----------------
__global__ void copy_kernel(const int* __restrict__ nei,
                            const float* __restrict__ ht,
                            const float* __restrict__ ct,
                            float* __restrict__ out) {
    int gid = blockIdx.x * 256 + threadIdx.x;   // M_ROWS*16 threads, float4 granules
    int row = gid >> 4;
    int q   = gid & 15;
    if (nei[row] > 0) return;
    size_t off = (size_t)row * 16 + q;
    const float4* h4 = (const float4*)ht;
    const float4* c4 = (const float4*)ct;
    float4* o = (float4*)out;
    o[off] = h4[off];
    o[OUT_HALF / 4 + off] = c4[off];
}

// ---------------- kernel 3: fused GEMM + LSTM epilogue (active rows) ----------------
__global__ void __launch_bounds__(256, 1)
gemm_kernel(const float* __restrict__ corr,
            const float* __restrict__ ht,
            const float* __restrict__ ct,
            const float* __restrict__ Wemb_g,
            const float* __restrict__ bemb_g,
            const float* __restrict__ Wih,
            const float* __restrict__ Whh,
            const float* __restrict__ bih,
            const float* __restrict__ bhh,
            float* __restrict__ out) {
    extern __shared__ float sm[];
    float* Wt   = sm;                          // [96][260]
    float* bias = Wt + KTOT * WT_STRIDE;       // [256]
    float* Wemb = bias + NGATES;               // [64]  (W_emb row-major [32][2])
    float* bemb = Wemb + 2 * EDIM;             // [32]
    float* At   = bemb + EDIM;                 // [96][64]  A transposed (k-major)
    int*   ridx = (int*)(At + KTOT * 64);      // [64]
    int*   tilebc = ridx + 64;                 // [1]

    const int tid = threadIdx.x;

    // ---- one-time weight staging (transposed; padded stride -> 4-way STS max) ----
    for (int i = tid; i < NGATES * EDIM; i += 256) {
        int n = i >> 5, k = i & 31;
        Wt[k * WT_STRIDE + n] = Wih[i];
    }
    for (int i = tid; i < NGATES * HDIM; i += 256) {
        int n = i >> 6, k = i & 63;
        Wt[(EDIM + k) * WT_STRIDE + n] = Whh[i];
    }
    if (tid < NGATES) bias[tid] = bih[tid] + bhh[tid];
    if (tid < 2 * EDIM) Wemb[tid] = Wemb_g[tid];
    if (tid < EDIM)     bemb[tid] = bemb_g[tid];

    const int count = g_cnt;
    const int tiles = (count + MTILE - 1) / MTILE;

    const int tc = tid & 31;      // gate group: n0 = 2*tc
    const int tr = tid >> 5;      // row group:  r0 = 8*tr (== warp id)
    const int n0 = tc * 2;
    const int r0 = tr * 8;

    const int fr  = tid & 63;     // fill row
    const int fch = tid >> 6;     // fill chunk 0..3

    while (true) {
        __syncthreads();  // everyone done with previous tile's At/ridx/tilebc
        if (tid == 0) tilebc[0] = atomicAdd(&g_tile, 1);
        __syncthreads();
        const int tile = tilebc[0];
        if (tile >= tiles) break;

        const int base = tile * MTILE;
        const int nr = min(MTILE, count - base);

        if (tid < MTILE) ridx[tid] = (tid < nr) ? g_list[base + tid] : 0;
        __syncthreads();

        // ---- build A^T tile: rows 0..31 = relu(emb), rows 32..95 = h ----
        {
            float x0 = 0.f, x1 = 0.f;
            if (fr < nr) {
                float2 xv = *(const float2*)(corr + (size_t)ridx[fr] * 2);
                x0 = xv.x; x1 = xv.y;
            }
            #pragma unroll
            for (int j = 0; j < 8; ++j) {
                int e = fch * 8 + j;
                float v = fmaxf(fmaf(x0, Wemb[2 * e], fmaf(x1, Wemb[2 * e + 1], bemb[e])), 0.f);
                At[e * 64 + fr] = (fr < nr) ? v : 0.f;   // lanes -> distinct banks
            }
            #pragma unroll
            for (int it = 0; it < 4; ++it) {
                int c4 = fch + it * 4;
                float4 v = make_float4(0.f, 0.f, 0.f, 0.f);
                if (fr < nr)
                    v = *(const float4*)(ht + (size_t)ridx[fr] * HDIM + c4 * 4);
                At[(EDIM + c4 * 4 + 0) * 64 + fr] = v.x;
                At[(EDIM + c4 * 4 + 1) * 64 + fr] = v.y;
                At[(EDIM + c4 * 4 + 2) * 64 + fr] = v.z;
                At[(EDIM + c4 * 4 + 3) * 64 + fr] = v.w;
            }
        }
        __syncthreads();

        // ---- main loop: 64 rows x 256 gates, 8x8 per thread, rows packed f32x2 ----
        unsigned long long acc[4][8];
        #pragma unroll
        for (int rp = 0; rp < 4; ++rp)
            #pragma unroll
            for (int j = 0; j < 8; ++j) acc[rp][j] = 0ull;

        #pragma unroll 2
        for (int k = 0; k < KTOT; ++k) {
            const float* arow = At + k * 64 + r0;
            float4 aA = *(const float4*)(arow);       // broadcast within warp
            float4 aB = *(const float4*)(arow + 4);
            unsigned long long ap[4] = {
                pk2(aA.x, aA.y), pk2(aA.z, aA.w),
                pk2(aB.x, aB.y), pk2(aB.z, aB.w)
            };
            const float* wrow = Wt + k * WT_STRIDE + n0;
            float2 b0 = *(const float2*)(wrow);         // i gates
            float2 b1 = *(const float2*)(wrow + 64);    // f
            float2 b2 = *(const float2*)(wrow + 128);   // g
            float2 b3 = *(const float2*)(wrow + 192);   // o
            unsigned long long bd[8] = {
                pk2(b0.x, b0.x), pk2(b0.y, b0.y),
                pk2(b1.x, b1.x), pk2(b1.y, b1.y),
                pk2(b2.x, b2.x), pk2(b2.y, b2.y),
                pk2(b3.x, b3.x), pk2(b3.y, b3.y)
            };
            #pragma unroll
            for (int rp = 0; rp < 4; ++rp)
                #pragma unroll
                for (int j = 0; j < 8; ++j)
                    acc[rp][j] = fma2(ap[rp], bd[j], acc[rp][j]);
        }

        // ---- epilogue: activations + mask scatter, register-resident ----
        const float bi0 = bias[n0],       bi1 = bias[n0 + 1];
        const float bf0 = bias[64 + n0],  bf1 = bias[64 + n0 + 1];
        const float bg0 = bias[128 + n0], bg1 = bias[128 + n0 + 1];
        const float bo0 = bias[192 + n0], bo1 = bias[192 + n0 + 1];

        #pragma unroll
        for (int rp = 0; rp < 4; ++rp) {
            #pragma unroll
            for (int s = 0; s < 2; ++s) {
                int r = r0 + rp * 2 + s;
                if (r < nr) {
                    int row = ridx[r];
                    float zi0 = (s ? get_hi(acc[rp][0]) : get_lo(acc[rp][0])) + bi0;
                    float zi1 = (s ? get_hi(acc[rp][1]) : get_lo(acc[rp][1])) + bi1;
                    float zf0 = (s ? get_hi(acc[rp][2]) : get_lo(acc[rp][2])) + bf0;
                    float zf1 = (s ? get_hi(acc[rp][3]) : get_lo(acc[rp][3])) + bf1;
                    float zg0 = (s ? get_hi(acc[rp][4]) : get_lo(acc[rp][4])) + bg0;
                    float zg1 = (s ? get_hi(acc[rp][5]) : get_lo(acc[rp][5])) + bg1;
                    float zo0 = (s ? get_hi(acc[rp][6]) : get_lo(acc[rp][6])) + bo0;
                    float zo1 = (s ? get_hi(acc[rp][7]) : get_lo(acc[rp][7])) + bo1;

                    float2 c2 = *(const float2*)(ct + (size_t)row * HDIM + n0);

                    float ii0 = sig_fast(zi0),  ii1 = sig_fast(zi1);
                    float ff0 = sig_fast(zf0),  ff1 = sig_fast(zf1);
                    float gg0 = tanh_fast(zg0), gg1 = tanh_fast(zg1);
                    float oo0 = sig_fast(zo0),  oo1 = sig_fast(zo1);

                    float cn0 = ff0 * c2.x + ii0 * gg0;
                    float cn1 = ff1 * c2.y + ii1 * gg1;
                    float hn0 = oo0 * tanh_fast(cn0);
                    float hn1 = oo1 * tanh_fast(cn1);

                    *(float2*)(out + (size_t)row * HDIM + n0) = make_float2(hn0, hn1);
                    *(float2*)(out + OUT_HALF + (size_t)row * HDIM + n0) = make_float2(cn0, cn1);
                }
            }
        }
    }
}

// ---------------- launch ----------------
extern "C" void kernel_launch(void* const* d_in, const int* in_sizes, int n_in,
                              void* d_out, int out_size) {
    const float* corr = (const float*)d_in[0];   // [P,P,2]
    const float* ht   = (const float*)d_in[1];   // [P,P,64]
    const float* ct   = (const float*)d_in[2];   // [P,P,64]
    const int*   nei  = (const int*)d_in[3];     // [P,P]
    const float* Wemb = (const float*)d_in[4];   // [32,2]
    const float* bemb = (const float*)d_in[5];   // [32]
    const float* Wih  = (const float*)d_in[6];   // [256,32]
    const float* Whh  = (const float*)d_in[7];   // [256,64]
    const float* bih  = (const float*)d_in[8];   // [256]
    const float* bhh  = (const float*)d_in[9];   // [256]
    float* out = (float*)d_out;                  // [h_out | c_out]

    const size_t smem_bytes =
        ((size_t)KTOT * WT_STRIDE + NGATES + 2 * EDIM + EDIM + (size_t)KTOT * 64) * sizeof(float)
        + (64 + 16) * sizeof(int);

    cudaFuncSetAttribute(gemm_kernel, cudaFuncAttributeMaxDynamicSharedMemorySize,
                         (int)smem_bytes);

    reset_kernel<<<1, 1>>>();
    compact_kernel<<<M_ROWS / 256, 256>>>(nei);
    copy_kernel<<<(M_ROWS * 16) / 256, 256>>>(nei, ht, ct, out);
    gemm_kernel<<<GEMM_GRID, 256, smem_bytes>>>(corr, ht, ct, Wemb, bemb,
                                                Wih, Whh, bih, bhh, out);
}

// round 14
// speedup vs baseline: 1.0022x; 1.0022x over previous
#include <cuda_runtime.h>

#define PED      512
#define M_ROWS   (PED*PED)          // 262144
#define HDIM     64
#define EDIM     32
#define KTOT     96                 // 32 emb + 64 h
#define NGATES   256
#define MTILE    64
#define WT_STRIDE 260               // padded to kill STS conflicts, keeps 8B align
#define OUT_HALF ((size_t)M_ROWS*HDIM)
#define GEMM_GRID 152

// ---------------- device scratch (no allocations allowed) ----------------
__device__ int g_cnt;
__device__ int g_tile;
__device__ int g_list[M_ROWS];

// ---------------- helpers ----------------
__device__ __forceinline__ unsigned long long pk2(float lo, float hi) {
    unsigned long long r;
    asm("mov.b64 %0, {%1,%2};" : "=l"(r)
        : "r"(__float_as_uint(lo)), "r"(__float_as_uint(hi)));
    return r;
}
__device__ __forceinline__ unsigned long long fma2(unsigned long long a,
                                                   unsigned long long b,
                                                   unsigned long long c) {
    unsigned long long d;
    asm("fma.rn.f32x2 %0, %1, %2, %3;" : "=l"(d) : "l"(a), "l"(b), "l"(c));
    return d;
}
__device__ __forceinline__ float get_lo(unsigned long long v) {
    unsigned lo, hi;
    asm("mov.b64 {%0,%1}, %2;" : "=r"(lo), "=r"(hi) : "l"(v));
    return __uint_as_float(lo);
}
__device__ __forceinline__ float get_hi(unsigned long long v) {
    unsigned lo, hi;
    asm("mov.b64 {%0,%1}, %2;" : "=r"(lo), "=r"(hi) : "l"(v));
    return __uint_as_float(hi);
}
__device__ __forceinline__ float sig_fast(float x) {
    return __fdividef(1.f, 1.f + __expf(-x));
}
__device__ __forceinline__ float tanh_fast(float x) {
    x = fminf(fmaxf(x, -15.f), 15.f);
    float e = __expf(2.f * x);
    return __fdividef(e - 1.f, e + 1.f);
}

// ---------------- kernel 0: reset counters ----------------
__global__ void reset_kernel() { g_cnt = 0; g_tile = 0; }

// ---------------- kernel 1: compact active rows (warp-aggregated) ----------------
__global__ void compact_kernel(const int* __restrict__ nei) {
    int row = blockIdx.x * 256 + threadIdx.x;   // grid covers exactly M_ROWS
    bool act = nei[row] > 0;
    unsigned m = __ballot_sync(0xffffffffu, act);
    int lane = threadIdx.x & 31;
    int base = 0;
    if (lane == 0) base = atomicAdd(&g_cnt, __popc(m));
    base = __shfl_sync(0xffffffffu, base, 0);
    if (act) g_list[base + __popc(m & ((1u << lane) - 1u))] = row;
}

// ---------------- kernel 2: copy inactive rows (h,c pass-through) ----------------
__global__ void copy_kernel(const int* __restrict__ nei,
                            const float* __restrict__ ht,
                            const float* __restrict__ ct,
                            float* __restrict__ out) {
    int gid = blockIdx.x * 256 + threadIdx.x;   // M_ROWS*16 threads, float4 granules
    int row = gid >> 4;
    int q   = gid & 15;
    if (nei[row] > 0) return;
    size_t off = (size_t)row * 16 + q;
    const float4* h4 = (const float4*)ht;
    const float4* c4 = (const float4*)ct;
    float4* o = (float4*)out;
    o[off] = h4[off];
    o[OUT_HALF / 4 + off] = c4[off];
}

// ---------------- kernel 3: fused GEMM + LSTM epilogue (active rows) ----------------
__global__ void __launch_bounds__(256, 1)
gemm_kernel(const float* __restrict__ corr,
            const float* __restrict__ ht,
            const float* __restrict__ ct,
            const float* __restrict__ Wemb_g,
            const float* __restrict__ bemb_g,
            const float* __restrict__ Wih,
            const float* __restrict__ Whh,
            const float* __restrict__ bih,
            const float* __restrict__ bhh,
            float* __restrict__ out) {
    extern __shared__ float sm[];
    float* Wt   = sm;                          // [96][260]
    float* bias = Wt + KTOT * WT_STRIDE;       // [256]
    float* Wemb = bias + NGATES;               // [64]  (W_emb row-major [32][2])
    float* bemb = Wemb + 2 * EDIM;             // [32]
    float* At   = bemb + EDIM;                 // [96][64]  A transposed (k-major)
    int*   ridx = (int*)(At + KTOT * 64);      // [64]
    int*   tilebc = ridx + 64;                 // [1]

    const int tid = threadIdx.x;

    // ---- one-time weight staging (transposed; padded stride -> 4-way STS max) ----
    for (int i = tid; i < NGATES * EDIM; i += 256) {
        int n = i >> 5, k = i & 31;
        Wt[k * WT_STRIDE + n] = Wih[i];
    }
    for (int i = tid; i < NGATES * HDIM; i += 256) {
        int n = i >> 6, k = i & 63;
        Wt[(EDIM + k) * WT_STRIDE + n] = Whh[i];
    }
    if (tid < NGATES) bias[tid] = bih[tid] + bhh[tid];
    if (tid < 2 * EDIM) Wemb[tid] = Wemb_g[tid];
    if (tid < EDIM)     bemb[tid] = bemb_g[tid];

    const int count = g_cnt;
    const int tiles = (count + MTILE - 1) / MTILE;

    const int tc = tid & 31;      // gate group: n0 = 2*tc
    const int tr = tid >> 5;      // row group:  r0 = 8*tr (== warp id)
    const int n0 = tc * 2;
    const int r0 = tr * 8;

    const int fr  = tid & 63;     // fill row
    const int fch = tid >> 6;     // fill chunk 0..3

    while (true) {
        __syncthreads();  // everyone done with previous tile's At/ridx/tilebc
        if (tid == 0) tilebc[0] = atomicAdd(&g_tile, 1);
        __syncthreads();
        const int tile = tilebc[0];
        if (tile >= tiles) break;

        const int base = tile * MTILE;
        const int nr = min(MTILE, count - base);

        if (tid < MTILE) ridx[tid] = (tid < nr) ? g_list[base + tid] : 0;
        __syncthreads();

        // ---- build A^T tile: rows 0..31 = relu(emb), rows 32..95 = h ----
        {
            float x0 = 0.f, x1 = 0.f;
            if (fr < nr) {
                float2 xv = *(const float2*)(corr + (size_t)ridx[fr] * 2);
                x0 = xv.x; x1 = xv.y;
            }
            #pragma unroll
            for (int j = 0; j < 8; ++j) {
                int e = fch * 8 + j;
                float v = fmaxf(fmaf(x0, Wemb[2 * e], fmaf(x1, Wemb[2 * e + 1], bemb[e])), 0.f);
                At[e * 64 + fr] = (fr < nr) ? v : 0.f;   // lanes -> distinct banks
            }
            #pragma unroll
            for (int it = 0; it < 4; ++it) {
                int c4 = fch + it * 4;
                float4 v = make_float4(0.f, 0.f, 0.f, 0.f);
                if (fr < nr)
                    v = *(const float4*)(ht + (size_t)ridx[fr] * HDIM + c4 * 4);
                At[(EDIM + c4 * 4 + 0) * 64 + fr] = v.x;
                At[(EDIM + c4 * 4 + 1) * 64 + fr] = v.y;
                At[(EDIM + c4 * 4 + 2) * 64 + fr] = v.z;
                At[(EDIM + c4 * 4 + 3) * 64 + fr] = v.w;
            }
        }
        __syncthreads();

        // ---- main loop: 64 rows x 256 gates, 8x8 per thread, rows packed f32x2 ----
        unsigned long long acc[4][8];
        #pragma unroll
        for (int rp = 0; rp < 4; ++rp)
            #pragma unroll
            for (int j = 0; j < 8; ++j) acc[rp][j] = 0ull;

        #pragma unroll 2
        for (int k = 0; k < KTOT; ++k) {
            const float* arow = At + k * 64 + r0;
            float4 aA = *(const float4*)(arow);       // broadcast within warp
            float4 aB = *(const float4*)(arow + 4);
            unsigned long long ap[4] = {
                pk2(aA.x, aA.y), pk2(aA.z, aA.w),
                pk2(aB.x, aB.y), pk2(aB.z, aB.w)
            };
            const float* wrow = Wt + k * WT_STRIDE + n0;
            float2 b0 = *(const float2*)(wrow);         // i gates
            float2 b1 = *(const float2*)(wrow + 64);    // f
            float2 b2 = *(const float2*)(wrow + 128);   // g
            float2 b3 = *(const float2*)(wrow + 192);   // o
            unsigned long long bd[8] = {
                pk2(b0.x, b0.x), pk2(b0.y, b0.y),
                pk2(b1.x, b1.x), pk2(b1.y, b1.y),
                pk2(b2.x, b2.x), pk2(b2.y, b2.y),
                pk2(b3.x, b3.x), pk2(b3.y, b3.y)
            };
            #pragma unroll
            for (int rp = 0; rp < 4; ++rp)
                #pragma unroll
                for (int j = 0; j < 8; ++j)
                    acc[rp][j] = fma2(ap[rp], bd[j], acc[rp][j]);
        }

        // ---- epilogue: activations + mask scatter, register-resident ----
        const float bi0 = bias[n0],       bi1 = bias[n0 + 1];
        const float bf0 = bias[64 + n0],  bf1 = bias[64 + n0 + 1];
        const float bg0 = bias[128 + n0], bg1 = bias[128 + n0 + 1];
        const float bo0 = bias[192 + n0], bo1 = bias[192 + n0 + 1];

        #pragma unroll
        for (int rp = 0; rp < 4; ++rp) {
            #pragma unroll
            for (int s = 0; s < 2; ++s) {
                int r = r0 + rp * 2 + s;
                if (r < nr) {
                    int row = ridx[r];
                    float zi0 = (s ? get_hi(acc[rp][0]) : get_lo(acc[rp][0])) + bi0;
                    float zi1 = (s ? get_hi(acc[rp][1]) : get_lo(acc[rp][1])) + bi1;
                    float zf0 = (s ? get_hi(acc[rp][2]) : get_lo(acc[rp][2])) + bf0;
                    float zf1 = (s ? get_hi(acc[rp][3]) : get_lo(acc[rp][3])) + bf1;
                    float zg0 = (s ? get_hi(acc[rp][4]) : get_lo(acc[rp][4])) + bg0;
                    float zg1 = (s ? get_hi(acc[rp][5]) : get_lo(acc[rp][5])) + bg1;
                    float zo0 = (s ? get_hi(acc[rp][6]) : get_lo(acc[rp][6])) + bo0;
                    float zo1 = (s ? get_hi(acc[rp][7]) : get_lo(acc[rp][7])) + bo1;

                    float2 c2 = *(const float2*)(ct + (size_t)row * HDIM + n0);

                    float ii0 = sig_fast(zi0),  ii1 = sig_fast(zi1);
                    float ff0 = sig_fast(zf0),  ff1 = sig_fast(zf1);
                    float gg0 = tanh_fast(zg0), gg1 = tanh_fast(zg1);
                    float oo0 = sig_fast(zo0),  oo1 = sig_fast(zo1);

                    float cn0 = ff0 * c2.x + ii0 * gg0;
                    float cn1 = ff1 * c2.y + ii1 * gg1;
                    float hn0 = oo0 * tanh_fast(cn0);
                    float hn1 = oo1 * tanh_fast(cn1);

                    *(float2*)(out + (size_t)row * HDIM + n0) = make_float2(hn0, hn1);
                    *(float2*)(out + OUT_HALF + (size_t)row * HDIM + n0) = make_float2(cn0, cn1);
                }
            }
        }
    }
}

// ---------------- launch ----------------
extern "C" void kernel_launch(void* const* d_in, const int* in_sizes, int n_in,
                              void* d_out, int out_size) {
    const float* corr = (const float*)d_in[0];   // [P,P,2]
    const float* ht   = (const float*)d_in[1];   // [P,P,64]
    const float* ct   = (const float*)d_in[2];   // [P,P,64]
    const int*   nei  = (const int*)d_in[3];     // [P,P]
    const float* Wemb = (const float*)d_in[4];   // [32,2]
    const float* bemb = (const float*)d_in[5];   // [32]
    const float* Wih  = (const float*)d_in[6];   // [256,32]
    const float* Whh  = (const float*)d_in[7];   // [256,64]
    const float* bih  = (const float*)d_in[8];   // [256]
    const float* bhh  = (const float*)d_in[9];   // [256]
    float* out = (float*)d_out;                  // [h_out | c_out]

    const size_t smem_bytes =
        ((size_t)KTOT * WT_STRIDE + NGATES + 2 * EDIM + EDIM + (size_t)KTOT * 64) * sizeof(float)
        + (64 + 16) * sizeof(int);

    cudaFuncSetAttribute(gemm_kernel, cudaFuncAttributeMaxDynamicSharedMemorySize,
                         (int)smem_bytes);

    reset_kernel<<<1, 1>>>();
    compact_kernel<<<M_ROWS / 256, 256>>>(nei);
    copy_kernel<<<(M_ROWS * 16) / 256, 256>>>(nei, ht, ct, out);
    gemm_kernel<<<GEMM_GRID, 256, smem_bytes>>>(corr, ht, ct, Wemb, bemb,
                                                Wih, Whh, bih, bhh, out);
}

// round 15
// speedup vs baseline: 1.0033x; 1.0012x over previous
#include <cuda_runtime.h>

#define PED      512
#define M_ROWS   (PED*PED)          // 262144
#define HDIM     64
#define EDIM     32
#define KTOT     96                 // 32 emb + 64 h
#define NGATES   256
#define MTILE    64
#define WT_STRIDE 260               // padded to kill STS conflicts, keeps 8B align
#define OUT_HALF ((size_t)M_ROWS*HDIM)
#define GEMM_GRID 152

// ---------------- device scratch (no allocations allowed) ----------------
__device__ int g_cnt;
__device__ int g_tile;
__device__ int g_list[M_ROWS];

// ---------------- helpers ----------------
__device__ __forceinline__ unsigned long long pk2(float lo, float hi) {
    unsigned long long r;
    asm("mov.b64 %0, {%1,%2};" : "=l"(r)
        : "r"(__float_as_uint(lo)), "r"(__float_as_uint(hi)));
    return r;
}
__device__ __forceinline__ unsigned long long fma2(unsigned long long a,
                                                   unsigned long long b,
                                                   unsigned long long c) {
    unsigned long long d;
    asm("fma.rn.f32x2 %0, %1, %2, %3;" : "=l"(d) : "l"(a), "l"(b), "l"(c));
    return d;
}
__device__ __forceinline__ float get_lo(unsigned long long v) {
    unsigned lo, hi;
    asm("mov.b64 {%0,%1}, %2;" : "=r"(lo), "=r"(hi) : "l"(v));
    return __uint_as_float(lo);
}
__device__ __forceinline__ float get_hi(unsigned long long v) {
    unsigned lo, hi;
    asm("mov.b64 {%0,%1}, %2;" : "=r"(lo), "=r"(hi) : "l"(v));
    return __uint_as_float(hi);
}
__device__ __forceinline__ float sig_fast(float x) {
    return __fdividef(1.f, 1.f + __expf(-x));
}
__device__ __forceinline__ float tanh_fast(float x) {
    x = fminf(fmaxf(x, -15.f), 15.f);
    float e = __expf(2.f * x);
    return __fdividef(e - 1.f, e + 1.f);
}

// ---------------- kernel 0: reset counters ----------------
__global__ void reset_kernel() { g_cnt = 0; g_tile = 0; }

// ---------------- kernel 1: compact active rows (warp-aggregated) ----------------
__global__ void compact_kernel(const int* __restrict__ nei) {
    int row = blockIdx.x * 256 + threadIdx.x;   // grid covers exactly M_ROWS
    bool act = nei[row] > 0;
    unsigned m = __ballot_sync(0xffffffffu, act);
    int lane = threadIdx.x & 31;
    int base = 0;
    if (lane == 0) base = atomicAdd(&g_cnt, __popc(m));
    base = __shfl_sync(0xffffffffu, base, 0);
    if (act) g_list[base + __popc(m & ((1u << lane) - 1u))] = row;
}

// ---------------- kernel 2: copy inactive rows (h,c pass-through) ----------------
__global__ void copy_kernel(const int* __restrict__ nei,
                            const float* __restrict__ ht,
                            const float* __restrict__ ct,
                            float* __restrict__ out) {
    int gid = blockIdx.x * 256 + threadIdx.x;   // M_ROWS*16 threads, float4 granules
    int row = gid >> 4;
    int q   = gid & 15;
    if (nei[row] > 0) return;
    size_t off = (size_t)row * 16 + q;
    const float4* h4 = (const float4*)ht;
    const float4* c4 = (const float4*)ct;
    float4* o = (float4*)out;
    o[off] = h4[off];
    o[OUT_HALF / 4 + off] = c4[off];
}

// ---------------- kernel 3: fused GEMM + LSTM epilogue (active rows) ----------------
__global__ void __launch_bounds__(256, 1)
gemm_kernel(const float* __restrict__ corr,
            const float* __restrict__ ht,
            const float* __restrict__ ct,
            const float* __restrict__ Wemb_g,
            const float* __restrict__ bemb_g,
            const float* __restrict__ Wih,
            const float* __restrict__ Whh,
            const float* __restrict__ bih,
            const float* __restrict__ bhh,
            float* __restrict__ out) {
    extern __shared__ float sm[];
    float* Wt   = sm;                          // [96][260]
    float* bias = Wt + KTOT * WT_STRIDE;       // [256]
    float* Wemb = bias + NGATES;               // [64]  (W_emb row-major [32][2])
    float* bemb = Wemb + 2 * EDIM;             // [32]
    float* At   = bemb + EDIM;                 // [96][64]  A transposed (k-major)
    int*   ridx = (int*)(At + KTOT * 64);      // [64]
    int*   tilebc = ridx + 64;                 // [1]

    const int tid = threadIdx.x;

    // ---- one-time weight staging (transposed; padded stride -> 4-way STS max) ----
    for (int i = tid; i < NGATES * EDIM; i += 256) {
        int n = i >> 5, k = i & 31;
        Wt[k * WT_STRIDE + n] = Wih[i];
    }
    for (int i = tid; i < NGATES * HDIM; i += 256) {
        int n = i >> 6, k = i & 63;
        Wt[(EDIM + k) * WT_STRIDE + n] = Whh[i];
    }
    if (tid < NGATES) bias[tid] = bih[tid] + bhh[tid];
    if (tid < 2 * EDIM) Wemb[tid] = Wemb_g[tid];
    if (tid < EDIM)     bemb[tid] = bemb_g[tid];

    const int count = g_cnt;
    const int tiles = (count + MTILE - 1) / MTILE;

    const int tc = tid & 31;      // gate group: n0 = 2*tc
    const int tr = tid >> 5;      // row group:  r0 = 8*tr (== warp id)
    const int n0 = tc * 2;
    const int r0 = tr * 8;

    const int fr  = tid & 63;     // fill row
    const int fch = tid >> 6;     // fill chunk 0..3

    while (true) {
        __syncthreads();  // everyone done with previous tile's At/ridx/tilebc
        if (tid == 0) tilebc[0] = atomicAdd(&g_tile, 1);
        __syncthreads();
        const int tile = tilebc[0];
        if (tile >= tiles) break;

        const int base = tile * MTILE;
        const int nr = min(MTILE, count - base);

        if (tid < MTILE) ridx[tid] = (tid < nr) ? g_list[base + tid] : 0;
        __syncthreads();

        // ---- build A^T tile: rows 0..31 = relu(emb), rows 32..95 = h ----
        {
            float x0 = 0.f, x1 = 0.f;
            if (fr < nr) {
                float2 xv = *(const float2*)(corr + (size_t)ridx[fr] * 2);
                x0 = xv.x; x1 = xv.y;
            }
            #pragma unroll
            for (int j = 0; j < 8; ++j) {
                int e = fch * 8 + j;
                float v = fmaxf(fmaf(x0, Wemb[2 * e], fmaf(x1, Wemb[2 * e + 1], bemb[e])), 0.f);
                At[e * 64 + fr] = (fr < nr) ? v : 0.f;   // lanes -> distinct banks
            }
            #pragma unroll
            for (int it = 0; it < 4; ++it) {
                int c4 = fch + it * 4;
                float4 v = make_float4(0.f, 0.f, 0.f, 0.f);
                if (fr < nr)
                    v = *(const float4*)(ht + (size_t)ridx[fr] * HDIM + c4 * 4);
                At[(EDIM + c4 * 4 + 0) * 64 + fr] = v.x;
                At[(EDIM + c4 * 4 + 1) * 64 + fr] = v.y;
                At[(EDIM + c4 * 4 + 2) * 64 + fr] = v.z;
                At[(EDIM + c4 * 4 + 3) * 64 + fr] = v.w;
            }
        }
        __syncthreads();

        // ---- main loop: 64 rows x 256 gates, 8x8 per thread, rows packed f32x2 ----
        unsigned long long acc[4][8];
        #pragma unroll
        for (int rp = 0; rp < 4; ++rp)
            #pragma unroll
            for (int j = 0; j < 8; ++j) acc[rp][j] = 0ull;

        #pragma unroll 2
        for (int k = 0; k < KTOT; ++k) {
            const float* arow = At + k * 64 + r0;
            float4 aA = *(const float4*)(arow);       // broadcast within warp
            float4 aB = *(const float4*)(arow + 4);
            unsigned long long ap[4] = {
                pk2(aA.x, aA.y), pk2(aA.z, aA.w),
                pk2(aB.x, aB.y), pk2(aB.z, aB.w)
            };
            const float* wrow = Wt + k * WT_STRIDE + n0;
            float2 b0 = *(const float2*)(wrow);         // i gates
            float2 b1 = *(const float2*)(wrow + 64);    // f
            float2 b2 = *(const float2*)(wrow + 128);   // g
            float2 b3 = *(const float2*)(wrow + 192);   // o
            unsigned long long bd[8] = {
                pk2(b0.x, b0.x), pk2(b0.y, b0.y),
                pk2(b1.x, b1.x), pk2(b1.y, b1.y),
                pk2(b2.x, b2.x), pk2(b2.y, b2.y),
                pk2(b3.x, b3.x), pk2(b3.y, b3.y)
            };
            #pragma unroll
            for (int rp = 0; rp < 4; ++rp)
                #pragma unroll
                for (int j = 0; j < 8; ++j)
                    acc[rp][j] = fma2(ap[rp], bd[j], acc[rp][j]);
        }

        // ---- epilogue: activations + mask scatter, register-resident ----
        const float bi0 = bias[n0],       bi1 = bias[n0 + 1];
        const float bf0 = bias[64 + n0],  bf1 = bias[64 + n0 + 1];
        const float bg0 = bias[128 + n0], bg1 = bias[128 + n0 + 1];
        const float bo0 = bias[192 + n0], bo1 = bias[192 + n0 + 1];

        #pragma unroll
        for (int rp = 0; rp < 4; ++rp) {
            #pragma unroll
            for (int s = 0; s < 2; ++s) {
                int r = r0 + rp * 2 + s;
                if (r < nr) {
                    int row = ridx[r];
                    float zi0 = (s ? get_hi(acc[rp][0]) : get_lo(acc[rp][0])) + bi0;
                    float zi1 = (s ? get_hi(acc[rp][1]) : get_lo(acc[rp][1])) + bi1;
                    float zf0 = (s ? get_hi(acc[rp][2]) : get_lo(acc[rp][2])) + bf0;
                    float zf1 = (s ? get_hi(acc[rp][3]) : get_lo(acc[rp][3])) + bf1;
                    float zg0 = (s ? get_hi(acc[rp][4]) : get_lo(acc[rp][4])) + bg0;
                    float zg1 = (s ? get_hi(acc[rp][5]) : get_lo(acc[rp][5])) + bg1;
                    float zo0 = (s ? get_hi(acc[rp][6]) : get_lo(acc[rp][6])) + bo0;
                    float zo1 = (s ? get_hi(acc[rp][7]) : get_lo(acc[rp][7])) + bo1;

                    float2 c2 = *(const float2*)(ct + (size_t)row * HDIM + n0);

                    float ii0 = sig_fast(zi0),  ii1 = sig_fast(zi1);
                    float ff0 = sig_fast(zf0),  ff1 = sig_fast(zf1);
                    float gg0 = tanh_fast(zg0), gg1 = tanh_fast(zg1);
                    float oo0 = sig_fast(zo0),  oo1 = sig_fast(zo1);

                    float cn0 = ff0 * c2.x + ii0 * gg0;
                    float cn1 = ff1 * c2.y + ii1 * gg1;
                    float hn0 = oo0 * tanh_fast(cn0);
                    float hn1 = oo1 * tanh_fast(cn1);

                    *(float2*)(out + (size_t)row * HDIM + n0) = make_float2(hn0, hn1);
                    *(float2*)(out + OUT_HALF + (size_t)row * HDIM + n0) = make_float2(cn0, cn1);
                }
            }
        }
    }
}

// ---------------- launch ----------------
extern "C" void kernel_launch(void* const* d_in, const int* in_sizes, int n_in,
                              void* d_out, int out_size) {
    const float* corr = (const float*)d_in[0];   // [P,P,2]
    const float* ht   = (const float*)d_in[1];   // [P,P,64]
    const float* ct   = (const float*)d_in[2];   // [P,P,64]
    const int*   nei  = (const int*)d_in[3];     // [P,P]
    const float* Wemb = (const float*)d_in[4];   // [32,2]
    const float* bemb = (const float*)d_in[5];   // [32]
    const float* Wih  = (const float*)d_in[6];   // [256,32]
    const float* Whh  = (const float*)d_in[7];   // [256,64]
    const float* bih  = (const float*)d_in[8];   // [256]
    const float* bhh  = (const float*)d_in[9];   // [256]
    float* out = (float*)d_out;                  // [h_out | c_out]

    const size_t smem_bytes =
        ((size_t)KTOT * WT_STRIDE + NGATES + 2 * EDIM + EDIM + (size_t)KTOT * 64) * sizeof(float)
        + (64 + 16) * sizeof(int);

    cudaFuncSetAttribute(gemm_kernel, cudaFuncAttributeMaxDynamicSharedMemorySize,
                         (int)smem_bytes);

    reset_kernel<<<1, 1>>>();
    compact_kernel<<<M_ROWS / 256, 256>>>(nei);
    copy_kernel<<<(M_ROWS * 16) / 256, 256>>>(nei, ht, ct, out);
    gemm_kernel<<<GEMM_GRID, 256, smem_bytes>>>(corr, ht, ct, Wemb, bemb,
                                                Wih, Whh, bih, bhh, out);
}

// round 16
// speedup vs baseline: 1.0054x; 1.0021x over previous
#include <cuda_runtime.h>

#define PED      512
#define M_ROWS   (PED*PED)          // 262144
#define HDIM     64
#define EDIM     32
#define KTOT     96                 // 32 emb + 64 h
#define NGATES   256
#define MTILE    64
#define WT_STRIDE 260               // padded to kill STS conflicts, keeps 8B align
#define OUT_HALF ((size_t)M_ROWS*HDIM)
#define GEMM_GRID 152

// ---------------- device scratch (no allocations allowed) ----------------
__device__ int g_cnt;
__device__ int g_tile;
__device__ int g_list[M_ROWS];

// ---------------- helpers ----------------
__device__ __forceinline__ unsigned long long pk2(float lo, float hi) {
    unsigned long long r;
    asm("mov.b64 %0, {%1,%2};" : "=l"(r)
        : "r"(__float_as_uint(lo)), "r"(__float_as_uint(hi)));
    return r;
}
__device__ __forceinline__ unsigned long long fma2(unsigned long long a,
                                                   unsigned long long b,
                                                   unsigned long long c) {
    unsigned long long d;
    asm("fma.rn.f32x2 %0, %1, %2, %3;" : "=l"(d) : "l"(a), "l"(b), "l"(c));
    return d;
}
__device__ __forceinline__ float get_lo(unsigned long long v) {
    unsigned lo, hi;
    asm("mov.b64 {%0,%1}, %2;" : "=r"(lo), "=r"(hi) : "l"(v));
    return __uint_as_float(lo);
}
__device__ __forceinline__ float get_hi(unsigned long long v) {
    unsigned lo, hi;
    asm("mov.b64 {%0,%1}, %2;" : "=r"(lo), "=r"(hi) : "l"(v));
    return __uint_as_float(hi);
}
__device__ __forceinline__ float sig_fast(float x) {
    return __fdividef(1.f, 1.f + __expf(-x));
}
__device__ __forceinline__ float tanh_fast(float x) {
    x = fminf(fmaxf(x, -15.f), 15.f);
    float e = __expf(2.f * x);
    return __fdividef(e - 1.f, e + 1.f);
}

// ---------------- kernel 0: reset counters ----------------
__global__ void reset_kernel() { g_cnt = 0; g_tile = 0; }

// ---------------- kernel 1: compact active rows (warp-aggregated) ----------------
__global__ void compact_kernel(const int* __restrict__ nei) {
    int row = blockIdx.x * 256 + threadIdx.x;   // grid covers exactly M_ROWS
    bool act = nei[row] > 0;
    unsigned m = __ballot_sync(0xffffffffu, act);
    int lane = threadIdx.x & 31;
    int base = 0;
    if (lane == 0) base = atomicAdd(&g_cnt, __popc(m));
    base = __shfl_sync(0xffffffffu, base, 0);
    if (act) g_list[base + __popc(m & ((1u << lane) - 1u))] = row;
}

// ---------------- kernel 2: copy inactive rows (h,c pass-through) ----------------
__global__ void copy_kernel(const int* __restrict__ nei,
                            const float* __restrict__ ht,
                            const float* __restrict__ ct,
                            float* __restrict__ out) {
    int gid = blockIdx.x * 256 + threadIdx.x;   // M_ROWS*16 threads, float4 granules
    int row = gid >> 4;
    int q   = gid & 15;
    if (nei[row] > 0) return;
    size_t off = (size_t)row * 16 + q;
    const float4* h4 = (const float4*)ht;
    const float4* c4 = (const float4*)ct;
    float4* o = (float4*)out;
    o[off] = h4[off];
    o[OUT_HALF / 4 + off] = c4[off];
}

// ---------------- kernel 3: fused GEMM + LSTM epilogue (active rows) ----------------
__global__ void __launch_bounds__(256, 1)
gemm_kernel(const float* __restrict__ corr,
            const float* __restrict__ ht,
            const float* __restrict__ ct,
            const float* __restrict__ Wemb_g,
            const float* __restrict__ bemb_g,
            const float* __restrict__ Wih,
            const float* __restrict__ Whh,
            const float* __restrict__ bih,
            const float* __restrict__ bhh,
            float* __restrict__ out) {
    extern __shared__ float sm[];
    float* Wt   = sm;                          // [96][260]
    float* bias = Wt + KTOT * WT_STRIDE;       // [256]
    float* Wemb = bias + NGATES;               // [64]  (W_emb row-major [32][2])
    float* bemb = Wemb + 2 * EDIM;             // [32]
    float* At   = bemb + EDIM;                 // [96][64]  A transposed (k-major)
    int*   ridx = (int*)(At + KTOT * 64);      // [64]
    int*   tilebc = ridx + 64;                 // [1]

    const int tid = threadIdx.x;

    // ---- one-time weight staging (transposed; padded stride -> 4-way STS max) ----
    for (int i = tid; i < NGATES * EDIM; i += 256) {
        int n = i >> 5, k = i & 31;
        Wt[k * WT_STRIDE + n] = Wih[i];
    }
    for (int i = tid; i < NGATES * HDIM; i += 256) {
        int n = i >> 6, k = i & 63;
        Wt[(EDIM + k) * WT_STRIDE + n] = Whh[i];
    }
    if (tid < NGATES) bias[tid] = bih[tid] + bhh[tid];
    if (tid < 2 * EDIM) Wemb[tid] = Wemb_g[tid];
    if (tid < EDIM)     bemb[tid] = bemb_g[tid];

    const int count = g_cnt;
    const int tiles = (count + MTILE - 1) / MTILE;

    const int tc = tid & 31;      // gate group: n0 = 2*tc
    const int tr = tid >> 5;      // row group:  r0 = 8*tr (== warp id)
    const int n0 = tc * 2;
    const int r0 = tr * 8;

    const int fr  = tid & 63;     // fill row
    const int fch = tid >> 6;     // fill chunk 0..3

    while (true) {
        __syncthreads();  // everyone done with previous tile's At/ridx/tilebc
        if (tid == 0) tilebc[0] = atomicAdd(&g_tile, 1);
        __syncthreads();
        const int tile = tilebc[0];
        if (tile >= tiles) break;

        const int base = tile * MTILE;
        const int nr = min(MTILE, count - base);

        if (tid < MTILE) ridx[tid] = (tid < nr) ? g_list[base + tid] : 0;
        __syncthreads();

        // ---- build A^T tile: rows 0..31 = relu(emb), rows 32..95 = h ----
        {
            float x0 = 0.f, x1 = 0.f;
            if (fr < nr) {
                float2 xv = *(const float2*)(corr + (size_t)ridx[fr] * 2);
                x0 = xv.x; x1 = xv.y;
            }
            #pragma unroll
            for (int j = 0; j < 8; ++j) {
                int e = fch * 8 + j;
                float v = fmaxf(fmaf(x0, Wemb[2 * e], fmaf(x1, Wemb[2 * e + 1], bemb[e])), 0.f);
                At[e * 64 + fr] = (fr < nr) ? v : 0.f;   // lanes -> distinct banks
            }
            #pragma unroll
            for (int it = 0; it < 4; ++it) {
                int c4 = fch + it * 4;
                float4 v = make_float4(0.f, 0.f, 0.f, 0.f);
                if (fr < nr)
                    v = *(const float4*)(ht + (size_t)ridx[fr] * HDIM + c4 * 4);
                At[(EDIM + c4 * 4 + 0) * 64 + fr] = v.x;
                At[(EDIM + c4 * 4 + 1) * 64 + fr] = v.y;
                At[(EDIM + c4 * 4 + 2) * 64 + fr] = v.z;
                At[(EDIM + c4 * 4 + 3) * 64 + fr] = v.w;
            }
        }
        __syncthreads();

        // ---- main loop: 64 rows x 256 gates, 8x8 per thread, rows packed f32x2 ----
        unsigned long long acc[4][8];
        #pragma unroll
        for (int rp = 0; rp < 4; ++rp)
            #pragma unroll
            for (int j = 0; j < 8; ++j) acc[rp][j] = 0ull;

        #pragma unroll 2
        for (int k = 0; k < KTOT; ++k) {
            const float* arow = At + k * 64 + r0;
            float4 aA = *(const float4*)(arow);       // broadcast within warp
            float4 aB = *(const float4*)(arow + 4);
            unsigned long long ap[4] = {
                pk2(aA.x, aA.y), pk2(aA.z, aA.w),
                pk2(aB.x, aB.y), pk2(aB.z, aB.w)
            };
            const float* wrow = Wt + k * WT_STRIDE + n0;
            float2 b0 = *(const float2*)(wrow);         // i gates
            float2 b1 = *(const float2*)(wrow + 64);    // f
            float2 b2 = *(const float2*)(wrow + 128);   // g
            float2 b3 = *(const float2*)(wrow + 192);   // o
            unsigned long long bd[8] = {
                pk2(b0.x, b0.x), pk2(b0.y, b0.y),
                pk2(b1.x, b1.x), pk2(b1.y, b1.y),
                pk2(b2.x, b2.x), pk2(b2.y, b2.y),
                pk2(b3.x, b3.x), pk2(b3.y, b3.y)
            };
            #pragma unroll
            for (int rp = 0; rp < 4; ++rp)
                #pragma unroll
                for (int j = 0; j < 8; ++j)
                    acc[rp][j] = fma2(ap[rp], bd[j], acc[rp][j]);
        }

        // ---- epilogue: activations + mask scatter, register-resident ----
        const float bi0 = bias[n0],       bi1 = bias[n0 + 1];
        const float bf0 = bias[64 + n0],  bf1 = bias[64 + n0 + 1];
        const float bg0 = bias[128 + n0], bg1 = bias[128 + n0 + 1];
        const float bo0 = bias[192 + n0], bo1 = bias[192 + n0 + 1];

        #pragma unroll
        for (int rp = 0; rp < 4; ++rp) {
            #pragma unroll
            for (int s = 0; s < 2; ++s) {
                int r = r0 + rp * 2 + s;
                if (r < nr) {
                    int row = ridx[r];
                    float zi0 = (s ? get_hi(acc[rp][0]) : get_lo(acc[rp][0])) + bi0;
                    float zi1 = (s ? get_hi(acc[rp][1]) : get_lo(acc[rp][1])) + bi1;
                    float zf0 = (s ? get_hi(acc[rp][2]) : get_lo(acc[rp][2])) + bf0;
                    float zf1 = (s ? get_hi(acc[rp][3]) : get_lo(acc[rp][3])) + bf1;
                    float zg0 = (s ? get_hi(acc[rp][4]) : get_lo(acc[rp][4])) + bg0;
                    float zg1 = (s ? get_hi(acc[rp][5]) : get_lo(acc[rp][5])) + bg1;
                    float zo0 = (s ? get_hi(acc[rp][6]) : get_lo(acc[rp][6])) + bo0;
                    float zo1 = (s ? get_hi(acc[rp][7]) : get_lo(acc[rp][7])) + bo1;

                    float2 c2 = *(const float2*)(ct + (size_t)row * HDIM + n0);

                    float ii0 = sig_fast(zi0),  ii1 = sig_fast(zi1);
                    float ff0 = sig_fast(zf0),  ff1 = sig_fast(zf1);
                    float gg0 = tanh_fast(zg0), gg1 = tanh_fast(zg1);
                    float oo0 = sig_fast(zo0),  oo1 = sig_fast(zo1);

                    float cn0 = ff0 * c2.x + ii0 * gg0;
                    float cn1 = ff1 * c2.y + ii1 * gg1;
                    float hn0 = oo0 * tanh_fast(cn0);
                    float hn1 = oo1 * tanh_fast(cn1);

                    *(float2*)(out + (size_t)row * HDIM + n0) = make_float2(hn0, hn1);
                    *(float2*)(out + OUT_HALF + (size_t)row * HDIM + n0) = make_float2(cn0, cn1);
                }
            }
        }
    }
}

// ---------------- launch ----------------
extern "C" void kernel_launch(void* const* d_in, const int* in_sizes, int n_in,
                              void* d_out, int out_size) {
    const float* corr = (const float*)d_in[0];   // [P,P,2]
    const float* ht   = (const float*)d_in[1];   // [P,P,64]
    const float* ct   = (const float*)d_in[2];   // [P,P,64]
    const int*   nei  = (const int*)d_in[3];     // [P,P]
    const float* Wemb = (const float*)d_in[4];   // [32,2]
    const float* bemb = (const float*)d_in[5];   // [32]
    const float* Wih  = (const float*)d_in[6];   // [256,32]
    const float* Whh  = (const float*)d_in[7];   // [256,64]
    const float* bih  = (const float*)d_in[8];   // [256]
    const float* bhh  = (const float*)d_in[9];   // [256]
    float* out = (float*)d_out;                  // [h_out | c_out]

    const size_t smem_bytes =
        ((size_t)KTOT * WT_STRIDE + NGATES + 2 * EDIM + EDIM + (size_t)KTOT * 64) * sizeof(float)
        + (64 + 16) * sizeof(int);

    cudaFuncSetAttribute(gemm_kernel, cudaFuncAttributeMaxDynamicSharedMemorySize,
                         (int)smem_bytes);

    reset_kernel<<<1, 1>>>();
    compact_kernel<<<M_ROWS / 256, 256>>>(nei);
    copy_kernel<<<(M_ROWS * 16) / 256, 256>>>(nei, ht, ct, out);
    gemm_kernel<<<GEMM_GRID, 256, smem_bytes>>>(corr, ht, ct, Wemb, bemb,
                                                Wih, Whh, bih, bhh, out);
}